// round 16
// baseline (speedup 1.0000x reference)
#include <cuda_runtime.h>
#include <cuda_bf16.h>
#include <cuda_fp16.h>
#include <math.h>

// ---------------- problem-size constants (fixed per dataset) ----------------
#define NMAX 100000
#define EMAX 3200000
#define F_IN 512
#define F_MID 16
#define F_OUT 64

// ---------------- scratch (static device allocations; no cudaMalloc) -------
__device__ int   g_is64;               // edge_index dtype flag (1 = int64)
__device__ int   g_cnt[NMAX];          // in-degree (excl self loop)
__device__ float g_dinv[NMAX];         // rsqrt(deg+1)
__device__ int   g_tile_pub[128];      // lookback: tile aggregate + 1 (0 = not ready)
__device__ int   g_rowptr[NMAX + 1];
__device__ int   g_cursor[NMAX];
__device__ int   g_col[EMAX];          // CSR source indices grouped by dst
__device__ __align__(16) float  g_hp[NMAX * F_MID];   // x@W1 (fp32, unscaled)
__device__ __align__(16) __half g_hph[NMAX * F_MID];  // (x@W1)*dinv in fp16
__device__ __align__(16) __half g_h1ph[NMAX * F_MID]; // relu(layer1)*dinv in fp16

// ---------------- init + dtype detection -------------------------------------
__global__ void k_init_detect(const long long* __restrict__ ei, int n) {
    int i = blockIdx.x * blockDim.x + threadIdx.x;
    if (i < n) g_cnt[i] = 0;
    if (i < 128) g_tile_pub[i] = 0;
    if (i == 0) {
        bool ok64 = true;
        #pragma unroll
        for (int t = 0; t < 16; t++) {
            long long v = ei[t];
            if (v < 0 || v >= NMAX) ok64 = false;
        }
        g_is64 = ok64 ? 1 : 0;
    }
}

// ---------------- degree count (16 edges / thread) ---------------------------
__global__ void k_count(const void* __restrict__ ei, int E) {
    long long e0 = (long long)(blockIdx.x * blockDim.x + threadIdx.x) * 16;
    if (e0 >= E) return;
    int d[16];
    if (e0 + 15 < E) {
        if (g_is64) {
            const longlong2* p = (const longlong2*)((const long long*)ei + E + e0);
            #pragma unroll
            for (int j = 0; j < 8; j++) {
                longlong2 v = p[j];
                d[2 * j] = (int)v.x; d[2 * j + 1] = (int)v.y;
            }
        } else {
            const int4* p = (const int4*)((const int*)ei + E + e0);
            #pragma unroll
            for (int j = 0; j < 4; j++) {
                int4 v = p[j];
                d[4 * j] = v.x; d[4 * j + 1] = v.y; d[4 * j + 2] = v.z; d[4 * j + 3] = v.w;
            }
        }
    } else {
        #pragma unroll
        for (int j = 0; j < 16; j++) {
            d[j] = -1;
            if (e0 + j < E)
                d[j] = g_is64 ? (int)((const long long*)ei)[E + e0 + j]
                              : ((const int*)ei)[E + e0 + j];
        }
    }
    #pragma unroll
    for (int j = 0; j < 16; j++)
        if ((unsigned)d[j] < NMAX) atomicAdd(&g_cnt[d[j]], 1);
}

// ---------------- single-pass scan with decoupled lookback ------------------
__global__ void k_scanAll(int n) {
    __shared__ int wsum[32];
    __shared__ int sprefix;
    const int lane = threadIdx.x & 31;
    const int wid  = threadIdx.x >> 5;
    const int b    = blockIdx.x;
    int idx = b * 1024 + threadIdx.x;
    int v = (idx < n) ? g_cnt[idx] : 0;
    if (idx < n) g_dinv[idx] = rsqrtf((float)(v + 1));  // +1 self loop

    int s = v;
    #pragma unroll
    for (int d = 1; d < 32; d <<= 1) {
        int t = __shfl_up_sync(0xffffffffu, s, d);
        if (lane >= d) s += t;
    }
    if (lane == 31) wsum[wid] = s;
    __syncthreads();
    if (wid == 0) {
        int w = wsum[lane];
        #pragma unroll
        for (int d = 1; d < 32; d <<= 1) {
            int t = __shfl_up_sync(0xffffffffu, w, d);
            if (lane >= d) w += t;
        }
        wsum[lane] = w;  // inclusive over warp sums
    }
    __syncthreads();
    if (wid > 0) s += wsum[wid - 1];

    if (threadIdx.x == 0) {
        ((volatile int*)g_tile_pub)[b] = wsum[31] + 1;  // publish aggregate
    }
    if (wid == 0) {
        int pre = 0;
        for (int j = lane; j < b; j += 32) {
            int p;
            do { p = ((volatile int*)g_tile_pub)[j]; } while (p == 0);
            pre += p - 1;
        }
        #pragma unroll
        for (int d = 16; d > 0; d >>= 1)
            pre += __shfl_xor_sync(0xffffffffu, pre, d);
        if (lane == 0) sprefix = pre;
    }
    __syncthreads();
    int excl = sprefix + s - v;
    if (idx < n) {
        g_rowptr[idx] = excl;
        g_cursor[idx] = excl;
        if (idx == n - 1) g_rowptr[n] = sprefix + s;
    }
}

// ---------------- CSR bucket fill (16 edges / thread) ------------------------
__global__ void k_fill(const void* __restrict__ ei, int E) {
    long long e0 = (long long)(blockIdx.x * blockDim.x + threadIdx.x) * 16;
    if (e0 >= E) return;
    int s[16], d[16];
    if (e0 + 15 < E) {
        if (g_is64) {
            const longlong2* ps = (const longlong2*)((const long long*)ei + e0);
            const longlong2* pd = (const longlong2*)((const long long*)ei + E + e0);
            #pragma unroll
            for (int j = 0; j < 8; j++) {
                longlong2 a = ps[j], b = pd[j];
                s[2 * j] = (int)a.x; s[2 * j + 1] = (int)a.y;
                d[2 * j] = (int)b.x; d[2 * j + 1] = (int)b.y;
            }
        } else {
            const int4* ps = (const int4*)((const int*)ei + e0);
            const int4* pd = (const int4*)((const int*)ei + E + e0);
            #pragma unroll
            for (int j = 0; j < 4; j++) {
                int4 a = ps[j], b = pd[j];
                s[4 * j] = a.x; s[4 * j + 1] = a.y; s[4 * j + 2] = a.z; s[4 * j + 3] = a.w;
                d[4 * j] = b.x; d[4 * j + 1] = b.y; d[4 * j + 2] = b.z; d[4 * j + 3] = b.w;
            }
        }
    } else {
        #pragma unroll
        for (int j = 0; j < 16; j++) {
            s[j] = -1; d[j] = -1;
            if (e0 + j < E) {
                if (g_is64) {
                    s[j] = (int)((const long long*)ei)[e0 + j];
                    d[j] = (int)((const long long*)ei)[E + e0 + j];
                } else {
                    s[j] = ((const int*)ei)[e0 + j];
                    d[j] = ((const int*)ei)[E + e0 + j];
                }
            }
        }
    }
    #pragma unroll
    for (int j = 0; j < 16; j++) {
        if ((unsigned)s[j] < NMAX && (unsigned)d[j] < NMAX) {
            int pos = atomicAdd(&g_cursor[d[j]], 1);
            g_col[pos] = s[j];
        }
    }
}

// ---------------- GEMM1 (v3, measured 59.5us): g_hp = x @ W1 (fp32) ---------
__global__ __launch_bounds__(256) void k_gemm1(const float* __restrict__ x,
                                               const float* __restrict__ W1,
                                               int n) {
    __shared__ __align__(16) float Xs[256][36];   // 36KB; pad 36 keeps 16B align
    __shared__ __align__(16) float Ws[32][16];    // 2KB K-chunk of W1
    const int tid = threadIdx.x;
    const int row0 = blockIdx.x * 256;
    const int r = tid >> 1;        // 0..127
    const int h = tid & 1;         // output half: 8 features each
    const int rA = r, rB = r + 128;

    unsigned long long a0 = 0ull, a1 = 0ull, a2 = 0ull, a3 = 0ull;  // row A
    unsigned long long b0 = 0ull, b1 = 0ull, b2 = 0ull, b3 = 0ull;  // row B

    unsigned int ws_base =
        (unsigned int)__cvta_generic_to_shared(&Ws[0][0]) + (unsigned int)(h * 32);

    for (int k0 = 0; k0 < F_IN; k0 += 32) {
        #pragma unroll
        for (int j = 0; j < 8; j++) {
            int lin = tid + 256 * j;            // 0..2047
            int rr = lin >> 3;                  // 0..255
            int cc = (lin & 7) << 2;            // 0,4,...,28
            int grow = row0 + rr;
            float4 v = make_float4(0.f, 0.f, 0.f, 0.f);
            if (grow < n)
                v = *reinterpret_cast<const float4*>(&x[(long long)grow * F_IN + k0 + cc]);
            *reinterpret_cast<float4*>(&Xs[rr][cc]) = v;
        }
        if (tid < 128)
            reinterpret_cast<float4*>(Ws)[tid] =
                reinterpret_cast<const float4*>(W1 + k0 * F_MID)[tid];
        __syncthreads();

        #pragma unroll
        for (int kk = 0; kk < 32; kk += 4) {
            float4 xa = *reinterpret_cast<const float4*>(&Xs[rA][kk]);
            float4 xb = *reinterpret_cast<const float4*>(&Xs[rB][kk]);
            const float xav[4] = {xa.x, xa.y, xa.z, xa.w};
            const float xbv[4] = {xb.x, xb.y, xb.z, xb.w};
            #pragma unroll
            for (int j = 0; j < 4; j++) {
                unsigned long long xxa, xxb, w01, w23, w45, w67;
                asm("mov.b64 %0, {%1, %1};" : "=l"(xxa) : "f"(xav[j]));
                asm("mov.b64 %0, {%1, %1};" : "=l"(xxb) : "f"(xbv[j]));
                unsigned int adr = ws_base + (unsigned int)((kk + j) * 64);
                asm("ld.shared.v2.b64 {%0, %1}, [%2];"
                    : "=l"(w01), "=l"(w23) : "r"(adr));
                asm("ld.shared.v2.b64 {%0, %1}, [%2];"
                    : "=l"(w45), "=l"(w67) : "r"(adr + 16));
                asm("fma.rn.f32x2 %0, %1, %2, %0;" : "+l"(a0) : "l"(xxa), "l"(w01));
                asm("fma.rn.f32x2 %0, %1, %2, %0;" : "+l"(a1) : "l"(xxa), "l"(w23));
                asm("fma.rn.f32x2 %0, %1, %2, %0;" : "+l"(a2) : "l"(xxa), "l"(w45));
                asm("fma.rn.f32x2 %0, %1, %2, %0;" : "+l"(a3) : "l"(xxa), "l"(w67));
                asm("fma.rn.f32x2 %0, %1, %2, %0;" : "+l"(b0) : "l"(xxb), "l"(w01));
                asm("fma.rn.f32x2 %0, %1, %2, %0;" : "+l"(b1) : "l"(xxb), "l"(w23));
                asm("fma.rn.f32x2 %0, %1, %2, %0;" : "+l"(b2) : "l"(xxb), "l"(w45));
                asm("fma.rn.f32x2 %0, %1, %2, %0;" : "+l"(b3) : "l"(xxb), "l"(w67));
            }
        }
        __syncthreads();
    }

    #pragma unroll
    for (int rowSel = 0; rowSel < 2; rowSel++) {
        int grow = row0 + (rowSel ? rB : rA);
        if (grow < n) {
            unsigned long long c0 = rowSel ? b0 : a0;
            unsigned long long c1 = rowSel ? b1 : a1;
            unsigned long long c2 = rowSel ? b2 : a2;
            unsigned long long c3 = rowSel ? b3 : a3;
            float f0, f1, f2, f3, f4, f5, f6, f7;
            asm("mov.b64 {%0, %1}, %2;" : "=f"(f0), "=f"(f1) : "l"(c0));
            asm("mov.b64 {%0, %1}, %2;" : "=f"(f2), "=f"(f3) : "l"(c1));
            asm("mov.b64 {%0, %1}, %2;" : "=f"(f4), "=f"(f5) : "l"(c2));
            asm("mov.b64 {%0, %1}, %2;" : "=f"(f6), "=f"(f7) : "l"(c3));
            float4* dst = reinterpret_cast<float4*>(&g_hp[(long long)grow * F_MID + h * 8]);
            dst[0] = make_float4(f0, f1, f2, f3);
            dst[1] = make_float4(f4, f5, f6, f7);
        }
    }
}

// ---------------- scale + convert to fp16 (side stream, overlaps k_fill) ----
// g_hph[v][f] = (half)(g_hp[v][f] * dinv[v])
__global__ void k_scale(int n) {
    int v = blockIdx.x * blockDim.x + threadIdx.x;
    if (v >= n) return;
    float dv = g_dinv[v];
    const float4* src = reinterpret_cast<const float4*>(&g_hp[v * F_MID]);
    float4 a = src[0], b = src[1], c = src[2], d = src[3];
    __half2 h[8];
    h[0] = __floats2half2_rn(a.x * dv, a.y * dv);
    h[1] = __floats2half2_rn(a.z * dv, a.w * dv);
    h[2] = __floats2half2_rn(b.x * dv, b.y * dv);
    h[3] = __floats2half2_rn(b.z * dv, b.w * dv);
    h[4] = __floats2half2_rn(c.x * dv, c.y * dv);
    h[5] = __floats2half2_rn(c.z * dv, c.w * dv);
    h[6] = __floats2half2_rn(d.x * dv, d.y * dv);
    h[7] = __floats2half2_rn(d.z * dv, d.w * dv);
    uint4* dst = reinterpret_cast<uint4*>(&g_hph[v * F_MID]);
    dst[0] = *reinterpret_cast<uint4*>(&h[0]);
    dst[1] = *reinterpret_cast<uint4*>(&h[4]);
}

// ---------------- fp16 gather helper ----------------------------------------
__device__ __forceinline__ void acc_half8(float* acc, const __half* p) {
    uint4 m = *reinterpret_cast<const uint4*>(p);
    const __half2* h2 = reinterpret_cast<const __half2*>(&m);
    #pragma unroll
    for (int j = 0; j < 4; j++) {
        float2 f = __half22float2(h2[j]);
        acc[2 * j]     += f.x;
        acc[2 * j + 1] += f.y;
    }
}

// ---------------- layer-1 aggregation: warp/node, 16 slots x 2 lanes --------
// h1p = (half)( relu(dinv*S + b1) * dinv )
__global__ __launch_bounds__(256) void k_agg1(const float* __restrict__ bias, int n) {
    const int warp = (blockIdx.x * blockDim.x + threadIdx.x) >> 5;
    const int lane = threadIdx.x & 31;
    if (warp >= n) return;
    const int v = warp;
    const int slot = lane >> 1;   // 0..15 edge slots
    const int c = lane & 1;       // feature half: 8 halves = 16B

    const int base = g_rowptr[v];
    const int end  = g_rowptr[v + 1];

    float acc[8] = {0.f, 0.f, 0.f, 0.f, 0.f, 0.f, 0.f, 0.f};
    for (int i = base + slot; i < end; i += 16) {
        int s = __ldg(&g_col[i]);
        acc_half8(acc, &g_hph[s * F_MID + c * 8]);
    }
    // reduce across the 16 slots (bits 1..4), c preserved
    #pragma unroll
    for (int d = 2; d < 32; d <<= 1) {
        #pragma unroll
        for (int f = 0; f < 8; f++)
            acc[f] += __shfl_xor_sync(0xffffffffu, acc[f], d);
    }
    if (lane < 2) {
        acc_half8(acc, &g_hph[v * F_MID + c * 8]);   // self loop
        float dv = g_dinv[v];
        float4 bb0 = *reinterpret_cast<const float4*>(&bias[c * 8]);
        float4 bb1 = *reinterpret_cast<const float4*>(&bias[c * 8 + 4]);
        const float bbv[8] = {bb0.x, bb0.y, bb0.z, bb0.w, bb1.x, bb1.y, bb1.z, bb1.w};
        __half2 h[4];
        #pragma unroll
        for (int j = 0; j < 4; j++) {
            float o0 = fmaxf(acc[2 * j] * dv + bbv[2 * j], 0.f) * dv;
            float o1 = fmaxf(acc[2 * j + 1] * dv + bbv[2 * j + 1], 0.f) * dv;
            h[j] = __floats2half2_rn(o0, o1);
        }
        *reinterpret_cast<uint4*>(&g_h1ph[v * F_MID + c * 8]) =
            *reinterpret_cast<uint4*>(&h[0]);
    }
}

// ---------------- layer-2 aggregation FUSED with output GEMM + log_softmax --
__global__ __launch_bounds__(256) void k_agg2_out(const float* __restrict__ W2,
                                                 const float* __restrict__ b2,
                                                 float* __restrict__ out, int n) {
    __shared__ float W2s[F_MID * F_OUT];  // 1024 floats
    {
        int tid = threadIdx.x;
        for (int i = tid; i < F_MID * F_OUT; i += 256) W2s[i] = W2[i];
    }
    __syncthreads();

    const int warp = (blockIdx.x * blockDim.x + threadIdx.x) >> 5;
    const int lane = threadIdx.x & 31;
    if (warp >= n) return;
    const int v = warp;
    const int slot = lane >> 1;
    const int c = lane & 1;

    const int base = g_rowptr[v];
    const int end  = g_rowptr[v + 1];

    float acc[8] = {0.f, 0.f, 0.f, 0.f, 0.f, 0.f, 0.f, 0.f};
    for (int i = base + slot; i < end; i += 16) {
        int s = __ldg(&g_col[i]);
        acc_half8(acc, &g_h1ph[s * F_MID + c * 8]);
    }
    #pragma unroll
    for (int d = 2; d < 32; d <<= 1) {
        #pragma unroll
        for (int f = 0; f < 8; f++)
            acc[f] += __shfl_xor_sync(0xffffffffu, acc[f], d);
    }
    if (lane < 2) {  // finalize s2 halves in lanes 0 (f0..7) and 1 (f8..15)
        acc_half8(acc, &g_h1ph[v * F_MID + c * 8]);  // self loop
        float dv = g_dinv[v];
        #pragma unroll
        for (int f = 0; f < 8; f++) acc[f] *= dv;
    }
    // broadcast 16 s2 values to all lanes
    float s2[F_MID];
    #pragma unroll
    for (int f = 0; f < 8; f++) {
        s2[f]     = __shfl_sync(0xffffffffu, acc[f], 0);
        s2[f + 8] = __shfl_sync(0xffffffffu, acc[f], 1);
    }
    // output GEMM: each lane computes feats (lane) and (lane+32)
    float a = b2[lane];
    float b = b2[lane + 32];
    #pragma unroll
    for (int f = 0; f < F_MID; f++) {
        a = fmaf(s2[f], W2s[f * F_OUT + lane], a);
        b = fmaf(s2[f], W2s[f * F_OUT + lane + 32], b);
    }
    float M = fmaxf(a, b);
    #pragma unroll
    for (int d = 16; d > 0; d >>= 1) M = fmaxf(M, __shfl_xor_sync(0xffffffffu, M, d));
    float sum = expf(a - M) + expf(b - M);
    #pragma unroll
    for (int d = 16; d > 0; d >>= 1) sum += __shfl_xor_sync(0xffffffffu, sum, d);
    float lz = M + logf(sum);
    out[(long long)v * F_OUT + lane]      = a - lz;
    out[(long long)v * F_OUT + lane + 32] = b - lz;
}

// ---------------- launch (fork/join: gemm+scale overlap CSR build) ----------
extern "C" void kernel_launch(void* const* d_in, const int* in_sizes, int n_in,
                              void* d_out, int out_size) {
    const float* x  = (const float*)d_in[0];
    const void*  ei = d_in[1];
    const float* W1 = (const float*)d_in[2];
    const float* b1 = (const float*)d_in[3];
    const float* W2 = (const float*)d_in[4];
    const float* b2 = (const float*)d_in[5];
    float*       out = (float*)d_out;

    const int n = in_sizes[0] / F_IN;          // 100000
    const int E = in_sizes[1] / 2;             // 3200000

    const int B = 256;
    const int nodeGrid  = (n + B - 1) / B;
    const int hexGrid   = (int)(((long long)E / 16 + B) / B);  // 16 edges / thread
    const int tiles     = (n + 1023) / 1024;
    const int warpGrid  = (n + 7) / 8;         // 8 warps per 256-thread block

    static cudaStream_t s1 = nullptr;
    static cudaEvent_t evFork = nullptr, evScan = nullptr, evJoin = nullptr;
    if (s1 == nullptr) {
        cudaStreamCreateWithFlags(&s1, cudaStreamNonBlocking);
        cudaEventCreateWithFlags(&evFork, cudaEventDisableTiming);
        cudaEventCreateWithFlags(&evScan, cudaEventDisableTiming);
        cudaEventCreateWithFlags(&evJoin, cudaEventDisableTiming);
    }

    // Fork: gemm1 (independent of edges) runs on s1 while the CSR build
    // chain runs on the main stream.
    cudaEventRecord(evFork, 0);
    cudaStreamWaitEvent(s1, evFork, 0);
    k_gemm1<<<(n + 255) / 256, B, 0, s1>>>(x, W1, n);

    k_init_detect<<<nodeGrid, B>>>((const long long*)ei, n);
    k_count<<<hexGrid, B>>>(ei, E);
    k_scanAll<<<tiles, 1024>>>(n);
    cudaEventRecord(evScan, 0);          // dinv ready

    // scale+convert on side stream (needs gemm + dinv), overlaps k_fill
    cudaStreamWaitEvent(s1, evScan, 0);
    k_scale<<<nodeGrid, B, 0, s1>>>(n);
    cudaEventRecord(evJoin, s1);

    k_fill<<<hexGrid, B>>>(ei, E);

    // Join: aggregation needs g_hph and the CSR.
    cudaStreamWaitEvent(0, evJoin, 0);
    k_agg1<<<warpGrid, B>>>(b1, n);
    k_agg2_out<<<warpGrid, B>>>(W2, b2, out, n);
}